// round 7
// baseline (speedup 1.0000x reference)
#include <cuda_runtime.h>
#include <cuda_fp16.h>

#define RR 128
#define BASIS 9
#define DATA_DIM 28
#define NUM_STEPS 256
#define STEP_SIZE 0.001f
#define BG 1.0f

#define NVOX (RR*RR*RR)           // 2097152

// 32 halves per voxel, split into two 32B lane-chunks:
//  Lane0 chunk (halves 0..15):  (c0_j, c1_j) pairs, j = 0..7
//  Lane1 chunk (halves 16..31): h16,h17 = (c0_8, c1_8)
//                               h18..h26 = c2_0..c2_8, h27 = 0
//                               h28 = sigma, h29..31 = 0
__device__ uint4 g_grid[NVOX * 4];     // 128 MiB

// ---------------------------------------------------------------------------
// Conversion: one thread per voxel. 7 aligned float4 reads, 4 uint4 writes.
// ---------------------------------------------------------------------------
__global__ void __launch_bounds__(256)
convert_kernel(const float* __restrict__ tree)
{
    int v = blockIdx.x * blockDim.x + threadIdx.x;
    if (v >= NVOX) return;
    const float4* s4 = reinterpret_cast<const float4*>(tree + (size_t)v * DATA_DIM);
    float f[28];
    #pragma unroll
    for (int k = 0; k < 7; ++k)
        *reinterpret_cast<float4*>(f + 4*k) = __ldg(s4 + k);

    __half h[32];
    #pragma unroll
    for (int j = 0; j < 8; ++j) {
        h[2*j]   = __float2half_rn(f[j]);        // c0_j
        h[2*j+1] = __float2half_rn(f[9 + j]);    // c1_j
    }
    h[16] = __float2half_rn(f[8]);               // c0_8
    h[17] = __float2half_rn(f[17]);              // c1_8
    #pragma unroll
    for (int k = 0; k < 9; ++k)
        h[18 + k] = __float2half_rn(f[18 + k]);  // c2_k
    h[27] = __float2half_rn(0.0f);
    h[28] = __float2half_rn(f[27]);              // sigma
    h[29] = h[30] = h[31] = __float2half_rn(0.0f);

    uint4* dst = g_grid + (size_t)v * 4;
    #pragma unroll
    for (int k = 0; k < 4; ++k)
        dst[k] = *reinterpret_cast<uint4*>(h + 8*k);
}

// ---------------------------------------------------------------------------
// Main renderer: 2 lanes per ray, depth-1 pipeline, HFMA2 shading
// ---------------------------------------------------------------------------
__global__ void __launch_bounds__(128)
volrend_kernel(const float* __restrict__ origins,
               const float* __restrict__ dirs,
               const float* __restrict__ viewdirs,
               const float* __restrict__ invradius,
               float* __restrict__ out,
               int nb)
{
    int tid = blockIdx.x * blockDim.x + threadIdx.x;
    int i = tid >> 1;          // ray index
    if (i >= nb) return;
    int p = tid & 1;           // lane within pair
    unsigned pmask = 3u << ((threadIdx.x & 31) & ~1);  // this pair's lanes

    float ox = origins[3*i+0], oy = origins[3*i+1], oz = origins[3*i+2];
    float dx = dirs[3*i+0],    dy = dirs[3*i+1],    dz = dirs[3*i+2];
    float inv_norm = rsqrtf(dx*dx + dy*dy + dz*dz);
    dx *= inv_norm; dy *= inv_norm; dz *= inv_norm;

    float vx = viewdirs[3*i+0], vy = viewdirs[3*i+1], vz = viewdirs[3*i+2];

    float sh[BASIS];
    sh[0] =  0.28209479177387814f;
    sh[1] = -0.4886025119029199f * vy;
    sh[2] =  0.4886025119029199f * vz;
    sh[3] = -0.4886025119029199f * vx;
    sh[4] =  1.0925484305920792f * vx * vy;
    sh[5] = -1.0925484305920792f * vy * vz;
    sh[6] =  0.31539156525252005f * (2.0f*vz*vz - vx*vx - vy*vy);
    sh[7] = -1.0925484305920792f * vx * vz;
    sh[8] =  0.5462742152960396f * (vx*vx - vy*vy);

    // Per-lane coefficient table (8 half2)
    __half2 cf[8];
    if (p == 0) {
        #pragma unroll
        for (int j = 0; j < 8; ++j) cf[j] = __floats2half2_rn(sh[j], sh[j]);
    } else {
        cf[0] = __floats2half2_rn(sh[8], sh[8]);  // * (c0_8, c1_8)
        cf[1] = __floats2half2_rn(sh[0], sh[1]);  // * (c2_0, c2_1)
        cf[2] = __floats2half2_rn(sh[2], sh[3]);
        cf[3] = __floats2half2_rn(sh[4], sh[5]);
        cf[4] = __floats2half2_rn(sh[6], sh[7]);
        cf[5] = __floats2half2_rn(sh[8], 0.0f);   // * (c2_8, 0)
        cf[6] = __floats2half2_rn(0.0f, 0.0f);    // * (sigma, 0) -> 0
        cf[7] = __floats2half2_rn(0.0f, 0.0f);
    }

    float idrx = 1.0f / (dx + 1e-9f);
    float idry = 1.0f / (dy + 1e-9f);
    float idrz = 1.0f / (dz + 1e-9f);

    float t1x = -ox * idrx, t2x = t1x + idrx;
    float t1y = -oy * idry, t2y = t1y + idry;
    float t1z = -oz * idrz, t2z = t1z + idrz;
    float tmin = fmaxf(fmaxf(fminf(t1x,t2x), fminf(t1y,t2y)), fminf(t1z,t2z));
    tmin = fmaxf(tmin, 0.0f);
    float tmax = fminf(fminf(fmaxf(t1x,t2x), fmaxf(t1y,t2y)), fmaxf(t1z,t2z));
    tmax = fminf(tmax, 1e9f);

    float irx = invradius[0], iry = invradius[1], irz = invradius[2];
    float dsx = dx / irx, dsy = dy / iry, dsz = dz / irz;
    float delta_scale = sqrtf(dsx*dsx + dsy*dsy + dsz*dsz);

    float oxR = ox * (float)RR, oyR = oy * (float)RR, ozR = oz * (float)RR;
    float dxR = dx * (float)RR, dyR = dy * (float)RR, dzR = dz * (float)RR;

    float t = tmin;
    float light = 1.0f;
    float out0 = 0.0f, out1 = 0.0f, out2 = 0.0f;
    const float cube_sz = 1.0f / (float)RR;

    #define GEOM(tt, dt_o, vp_o)                                               \
    {                                                                          \
        float px = fmaf((tt), dxR, oxR);                                       \
        float py = fmaf((tt), dyR, oyR);                                       \
        float pz = fmaf((tt), dzR, ozR);                                       \
        float fx = fminf(fmaxf(floorf(px), 0.0f), (float)(RR-1));              \
        float fy = fminf(fmaxf(floorf(py), 0.0f), (float)(RR-1));              \
        float fz = fminf(fmaxf(floorf(pz), 0.0f), (float)(RR-1));              \
        int flat = (int)fmaf(fx, 16384.0f, fmaf(fy, 128.0f, fz));              \
        (vp_o) = g_grid + (size_t)flat * 4;                                    \
        float cx = px - fx, cy = py - fy, cz = pz - fz;                        \
        float u1x = -cx * idrx, u2x = u1x + idrx;                              \
        float u1y = -cy * idry, u2y = u1y + idry;                              \
        float u1z = -cz * idrz, u2z = u1z + idrz;                              \
        float s0 = fmaxf(fmaxf(fminf(u1x,u2x), fminf(u1y,u2y)), fminf(u1z,u2z)); \
        s0 = fmaxf(s0, 0.0f);                                                  \
        float s1 = fminf(fminf(fmaxf(u1x,u2x), fmaxf(u1y,u2y)), fmaxf(u1z,u2z)); \
        s1 = fminf(s1, 1e9f);                                                  \
        (dt_o) = (s1 - s0) * cube_sz + STEP_SIZE;                              \
    }

    if (tmin < tmax) {
        float dt_cur;
        const uint4* vp;
        GEOM(t, dt_cur, vp);
        // Each lane loads its own 32B half of the 64B voxel record.
        uint4 b0 = __ldg(vp + 2*p);
        uint4 b1 = __ldg(vp + 2*p + 1);

        #pragma unroll 1
        for (int s = 0; s < NUM_STEPS; ++s) {
            uint4 a0 = b0, a1 = b1;
            float dt = dt_cur;

            // Prefetch next step before shading
            float t_new = t + dt;
            bool more = (t_new < tmax) && (s + 1 < NUM_STEPS);
            float dt_next = 0.0f;
            if (more) {
                const uint4* vpn;
                GEOM(t_new, dt_next, vpn);
                b0 = __ldg(vpn + 2*p);
                b1 = __ldg(vpn + 2*p + 1);
            }

            // Shade (branchless per-lane halves)
            __half2 v[8];
            *reinterpret_cast<uint4*>(v)     = a0;
            *reinterpret_cast<uint4*>(v + 4) = a1;

            __half2 acc_a = __hmul2(cf[0], v[0]);
            __half2 acc_b = __floats2half2_rn(0.0f, 0.0f);
            #pragma unroll
            for (int j = 1; j < 8; ++j)
                acc_b = __hfma2(cf[j], v[j], acc_b);

            // lane0: (c0,c1) = acc_a + acc_b ; lane1: (c0_8 part) = acc_a, c2 = acc_b
            __half2 zero2 = __floats2half2_rn(0.0f, 0.0f);
            __half2 c01_loc = __hadd2(acc_a, p ? zero2 : acc_b);
            float2 bb = __half22float2(acc_b);
            float c2_loc  = p ? (bb.x + bb.y) : 0.0f;
            float sig_loc = p ? __half2float(__low2half(v[6])) : 0.0f;

            // Pair exchange: everyone ends with full c0, c1, c2, sigma
            unsigned u01 = *reinterpret_cast<unsigned*>(&c01_loc);
            unsigned uo  = __shfl_xor_sync(pmask, u01, 1);
            __half2 c01h = __hadd2(c01_loc, *reinterpret_cast<__half2*>(&uo));
            float c2    = c2_loc  + __shfl_xor_sync(pmask, c2_loc,  1);
            float sigma = sig_loc + __shfl_xor_sync(pmask, sig_loc, 1);
            sigma = fmaxf(sigma, 0.0f);

            float2 c01 = __half22float2(c01h);

            float att = __expf(-dt * sigma * delta_scale);
            float weight = light * (1.0f - att);

            float r0 = __fdividef(1.0f, 1.0f + __expf(-c01.x));
            float r1 = __fdividef(1.0f, 1.0f + __expf(-c01.y));
            float r2 = __fdividef(1.0f, 1.0f + __expf(-c2));

            out0 = fmaf(weight, r0, out0);
            out1 = fmaf(weight, r1, out1);
            out2 = fmaf(weight, r2, out2);
            light *= att;

            t = t_new;
            dt_cur = dt_next;
            if (!more) break;
        }
    }
    #undef GEOM

    if (p == 0) {
        out[3*i+0] = out0 + light * BG;
        out[3*i+1] = out1 + light * BG;
        out[3*i+2] = out2 + light * BG;
    }
}

extern "C" void kernel_launch(void* const* d_in, const int* in_sizes, int n_in,
                              void* d_out, int out_size)
{
    const float* tree      = (const float*)d_in[0];
    const float* origins   = (const float*)d_in[1];
    const float* dirs      = (const float*)d_in[2];
    const float* viewdirs  = (const float*)d_in[3];
    const float* invradius = (const float*)d_in[4];
    float* out = (float*)d_out;

    int nb = in_sizes[1] / 3;

    convert_kernel<<<(NVOX + 255) / 256, 256>>>(tree);

    int threads = 128;
    long long total = 2LL * nb;
    int blocks = (int)((total + threads - 1) / threads);
    volrend_kernel<<<blocks, threads>>>(origins, dirs, viewdirs, invradius, out, nb);
}